// round 11
// baseline (speedup 1.0000x reference)
#include <cuda_runtime.h>
#include <cuda_bf16.h>

// Batched FWHT, N = 4096, scale 1/64. One CTA/row, single HBM pass.
//
// Wavefront-minimal plan (per CTA, 8 warps):
//   load : e = t | k<<8          LDG.32 x16, fully coalesced    -> 128 wf
//   ex1  : w1 = e ^ ((e>>4)&31)  STS/LDS.32, conflict-free      -> 256 wf
//   ex2  : w2 = e ^ ((e>>5)&15) ^ (e8<<4)  STS/LDS.32 CF        -> 256 wf
//   store: e = (t&15)|r<<4|(t>>4)<<8  two 64B runs/instr        -> 256 wf
// Phases (in-register H16, pure FADD): P1 e[8:12], P2 e[0:4], P3 e[4:8].
//
// __launch_bounds__(256, 8): clamp to 32 regs -> 8 CTAs/SM, 64 warps (full
// occupancy). Latency exposure across the serial phase chain was the R10
// limiter (occ 69%, DRAM 60%).

#define FWHT_N  4096
#define THREADS 256

__device__ __forceinline__ void h16(float v[16]) {
#pragma unroll
    for (int st = 1; st < 16; st <<= 1)
#pragma unroll
        for (int i = 0; i < 16; i++)
            if ((i & st) == 0) {
                float a = v[i], b = v[i | st];
                v[i]      = a + b;
                v[i | st] = a - b;
            }
}

__global__ __launch_bounds__(THREADS, 8) void fwht4096_kernel(
    const float* __restrict__ x, float* __restrict__ y)
{
    __shared__ float s[FWHT_N];

    const int t = threadIdx.x;
    const size_t base = (size_t)blockIdx.x * FWHT_N;

    float v[16];

    // ---- Load: e = t | k<<8, reg k = e[8:12]. Coalesced LDG.32 x16. ----
    {
        const float* xr = x + base + t;
#pragma unroll
        for (int k = 0; k < 16; k++)
            v[k] = xr[k << 8];
    }

    // ---- P1: H16 on e[8:12] ----
    h16(v);

    // ---- Exchange 1 store: e = t | k<<8, swz1 = e ^ ((e>>4)&31).
    //      t-part hoisted; k-part is a literal XOR per iteration. ----
    {
        const int b1s = t ^ ((t >> 4) & 15);          // t-only part
#pragma unroll
        for (int k = 0; k < 16; k++)
            s[b1s ^ (k << 8) ^ ((k & 1) << 4)] = v[k];
    }
    __syncthreads();

    // ---- Exchange 1 load: e = j | t<<4, swz1 = e ^ (t&31). ----
    {
        const int b1l = (t << 4) ^ (t & 31);
#pragma unroll
        for (int j = 0; j < 16; j++)
            v[j] = s[b1l ^ j];
    }

    // ---- P2: H16 on e[0:4] ----
    h16(v);
    __syncthreads();

    // ---- Exchange 2 store: e = j | t<<4,
    //      swz2 = e ^ ((t>>1)&15) ^ (((t>>4)&1)<<4). All t-only. ----
    {
        const int b2s = (t << 4) ^ ((t >> 1) & 15) ^ (((t >> 4) & 1) << 4);
#pragma unroll
        for (int j = 0; j < 16; j++)
            s[b2s ^ j] = v[j];
    }
    __syncthreads();

    // ---- Exchange 2 load: e = (t&15) | r<<4 | (t>>4)<<8,
    //      swz2 xor-term: r-part ((r>>1)&7) is a literal; t-part hoisted. ----
    {
        const int b2l = ((t & 15) | ((t >> 4) << 8))
                      ^ (((t >> 4) & 1) << 3) ^ (((t >> 4) & 1) << 4);
#pragma unroll
        for (int r = 0; r < 16; r++)
            v[r] = s[b2l ^ (r << 4) ^ ((r >> 1) & 7)];
    }

    // ---- P3: H16 on e[4:8] ----
    h16(v);

    // ---- Store: e = (t&15) | r<<4 | (t>>4)<<8, scale 1/64. ----
    {
        const float c = 1.0f / 64.0f;
        float* yr = y + base + (t & 15) + ((t >> 4) << 8);
#pragma unroll
        for (int r = 0; r < 16; r++)
            yr[r << 4] = v[r] * c;
    }
}

extern "C" void kernel_launch(void* const* d_in, const int* in_sizes, int n_in,
                              void* d_out, int out_size) {
    const float* x = (const float*)d_in[0];
    float* y = (float*)d_out;
    const int rows = in_sizes[0] / FWHT_N;   // 8192
    fwht4096_kernel<<<rows, THREADS>>>(x, y);
}